// round 1
// baseline (speedup 1.0000x reference)
#include <cuda_runtime.h>
#include <math.h>

// Problem dims (fixed by the dataset)
#define BB 32
#define DD 1024
#define HH 1024

#define GEMM_BLOCKS 16      // h-tiles of 64: 1024/64
#define STREAM_BLOCKS 1168
#define NTHREADS 256

// d_out layout (float32, reference return order):
//   out   [B,H]      @ 0
//   u_new [B,H]      @ 32768
//   E_w   [B,D,H]    @ 65536
//   E_b   [B,H]      @ 65536 + 33554432
#define OFF_UNEW (BB*HH)
#define OFF_EW   (2*BB*HH)
#define OFF_EB   (2*BB*HH + BB*DD*HH)

__global__ void diag_rtrl_fused_kernel(
    const float* __restrict__ x,   // [B,D]
    const float* __restrict__ w,   // [D,H]
    const float* __restrict__ b,   // [H]
    const float* __restrict__ u,   // [B,H]
    const float* __restrict__ Ew,  // [1,B,D,H]
    const float* __restrict__ Eb,  // [1,B,H]
    float* __restrict__ out)       // packed outputs
{
    if (blockIdx.x < GEMM_BLOCKS) {
        // ---------------- GEMM + epilogue path ----------------
        // block handles h-tile of 64 columns, all 32 batch rows.
        __shared__ float xs[32][33];                  // [i][k] (+pad)
        __shared__ __align__(16) float ws[32][64];    // [k][h]

        const int t  = threadIdx.x;
        const int h0 = blockIdx.x * 64;
        const int hx = t & 15;          // which float4 of the h-tile
        const int iy = t >> 4;          // 0..15 -> batch-row pair
        const int i0 = iy * 2;

        float4 acc0 = make_float4(0.f, 0.f, 0.f, 0.f);
        float4 acc1 = make_float4(0.f, 0.f, 0.f, 0.f);

        for (int kt = 0; kt < DD; kt += 32) {
            // load x tile: 32 rows x 32 k (coalesced: 32 floats per row)
            for (int m = t; m < 1024; m += NTHREADS) {
                xs[m >> 5][m & 31] = x[(m >> 5) * DD + kt + (m & 31)];
            }
            // load w tile: 32 k x 64 h (coalesced)
            for (int m = t; m < 2048; m += NTHREADS) {
                ws[m >> 6][m & 63] = w[(kt + (m >> 6)) * HH + h0 + (m & 63)];
            }
            __syncthreads();

            #pragma unroll 8
            for (int k = 0; k < 32; k++) {
                float4 wv = reinterpret_cast<const float4*>(&ws[k][0])[hx];
                float x0 = xs[i0][k];
                float x1 = xs[i0 + 1][k];
                acc0.x = fmaf(x0, wv.x, acc0.x);
                acc0.y = fmaf(x0, wv.y, acc0.y);
                acc0.z = fmaf(x0, wv.z, acc0.z);
                acc0.w = fmaf(x0, wv.w, acc0.w);
                acc1.x = fmaf(x1, wv.x, acc1.x);
                acc1.y = fmaf(x1, wv.y, acc1.y);
                acc1.z = fmaf(x1, wv.z, acc1.z);
                acc1.w = fmaf(x1, wv.w, acc1.w);
            }
            __syncthreads();
        }

        // epilogue: z = 0.9*u + x@w + b ; out = tanh(z); u_new = z; E_b update
        const int h = h0 + hx * 4;
        float4 bv = *reinterpret_cast<const float4*>(&b[h]);

        #pragma unroll
        for (int ii = 0; ii < 2; ii++) {
            const int i = i0 + ii;
            const int idx = i * HH + h;
            float4 a  = ii ? acc1 : acc0;
            float4 uv = *reinterpret_cast<const float4*>(&u[idx]);
            float4 z;
            z.x = fmaf(0.9f, uv.x, a.x + bv.x);
            z.y = fmaf(0.9f, uv.y, a.y + bv.y);
            z.z = fmaf(0.9f, uv.z, a.z + bv.z);
            z.w = fmaf(0.9f, uv.w, a.w + bv.w);

            // u_new
            *reinterpret_cast<float4*>(&out[OFF_UNEW + idx]) = z;
            // out = tanh(z)
            float4 o;
            o.x = tanhf(z.x); o.y = tanhf(z.y);
            o.z = tanhf(z.z); o.w = tanhf(z.w);
            *reinterpret_cast<float4*>(&out[idx]) = o;
            // E_b_new = 0.9*E_b + 1
            float4 ev = *reinterpret_cast<const float4*>(&Eb[idx]);
            float4 e;
            e.x = fmaf(0.9f, ev.x, 1.0f);
            e.y = fmaf(0.9f, ev.y, 1.0f);
            e.z = fmaf(0.9f, ev.z, 1.0f);
            e.w = fmaf(0.9f, ev.w, 1.0f);
            *reinterpret_cast<float4*>(&out[OFF_EB + idx]) = e;
        }
    } else {
        // ---------------- E_w streaming path ----------------
        // E_new_w[i,d,h] = 0.9*E_w[i,d,h] + x[i,d]
        // float4 index p -> element 4p -> x index (4p)>>10 = p>>8
        const int N4 = (BB * DD * HH) / 4;  // 8388608
        const float4* ein = reinterpret_cast<const float4*>(Ew);
        float4* eo = reinterpret_cast<float4*>(&out[OFF_EW]);

        const int stride = (gridDim.x - GEMM_BLOCKS) * NTHREADS;
        int p = (blockIdx.x - GEMM_BLOCKS) * NTHREADS + threadIdx.x;

        for (; p < N4; p += stride) {
            float4 e = __ldcs(ein + p);
            float xv = __ldg(&x[p >> 8]);
            float4 r;
            r.x = fmaf(0.9f, e.x, xv);
            r.y = fmaf(0.9f, e.y, xv);
            r.z = fmaf(0.9f, e.z, xv);
            r.w = fmaf(0.9f, e.w, xv);
            __stcs(eo + p, r);
        }
    }
}

extern "C" void kernel_launch(void* const* d_in, const int* in_sizes, int n_in,
                              void* d_out, int out_size) {
    const float* x  = (const float*)d_in[0];  // [32,1024]
    const float* w  = (const float*)d_in[1];  // [1024,1024]
    const float* b  = (const float*)d_in[2];  // [1024]
    const float* u  = (const float*)d_in[3];  // [32,1024]
    const float* Ew = (const float*)d_in[4];  // [1,32,1024,1024]
    const float* Eb = (const float*)d_in[5];  // [1,32,1024]
    float* out = (float*)d_out;

    diag_rtrl_fused_kernel<<<GEMM_BLOCKS + STREAM_BLOCKS, NTHREADS>>>(
        x, w, b, u, Ew, Eb, out);
}